// round 9
// baseline (speedup 1.0000x reference)
#include <cuda_runtime.h>

typedef unsigned long long ull;

#define T10 10
#define NT  20
#define NW  3
#define D   128
#define H   8
#define R   24        // H*NW
#define NBATCH 32768
#define TPA 128       // attn kernel threads
#define GPA 2         // batches per attn CTA
#define TPB 512       // ffn kernel threads (16 warps)
#define NB  16        // batches per ffn CTA

// ---------------- device scratch ----------------
__device__ __align__(16) float g_QWr[R][D];
__device__ float g_sbias[R];
__device__ __align__(16) float g_queries[NW][D];
// pair-interleaved weights over reduction dim k: (k2, n) = (W_t[2k2][n], W_t[2k2+1][n])
__device__ __align__(16) float2 g_wv_p[64][128];
__device__ __align__(16) float2 g_op_p[64][128];
__device__ __align__(16) float2 g_fc1_p[64][256];
__device__ __align__(16) float2 g_fc2_p[128][128];
// attention-weighted tokens (intermediate), 402 MB scratch
__device__ __align__(16) float g_wt[NBATCH][R][D];

// ---------------- f32x2 helpers ----------------
__device__ __forceinline__ void ffma2(ull& d, ull a, ull b) {
    asm("fma.rn.f32x2 %0, %1, %2, %0;" : "+l"(d) : "l"(a), "l"(b));
}
__device__ __forceinline__ float foldp(ull v) {
    float2 f = *reinterpret_cast<float2*>(&v);
    return f.x + f.y;
}

// ---------------- weight prep ----------------
__global__ void prep_weights(const float* __restrict__ in_proj_w,
                             const float* __restrict__ out_proj_w,
                             const float* __restrict__ fc1_w,
                             const float* __restrict__ fc2_w)
{
    int idx = blockIdx.x * blockDim.x + threadIdx.x;
    int stride = gridDim.x * blockDim.x;
    for (int i = idx; i < 64 * 128; i += stride) {
        int k2 = i >> 7, n = i & 127;
        g_wv_p[k2][n] = make_float2(in_proj_w[(2 * D + n) * D + 2 * k2],
                                    in_proj_w[(2 * D + n) * D + 2 * k2 + 1]);
        g_op_p[k2][n] = make_float2(out_proj_w[n * D + 2 * k2],
                                    out_proj_w[n * D + 2 * k2 + 1]);
    }
    for (int i = idx; i < 64 * 256; i += stride) {
        int k2 = i >> 8, n = i & 255;
        g_fc1_p[k2][n] = make_float2(fc1_w[n * D + 2 * k2], fc1_w[n * D + 2 * k2 + 1]);
    }
    for (int i = idx; i < 128 * 128; i += stride) {
        int k2 = i >> 7, n = i & 127;
        g_fc2_p[k2][n] = make_float2(fc2_w[n * 2 * D + 2 * k2], fc2_w[n * 2 * D + 2 * k2 + 1]);
    }
}

// ---------------- precompute: query LN, q, QW, score bias ----------------
__global__ void precompute_kernel(const float* __restrict__ query_emb,
                                  const float* __restrict__ qg,
                                  const float* __restrict__ qb,
                                  const float* __restrict__ in_proj_w,
                                  const float* __restrict__ in_proj_b)
{
    __shared__ float sq[NW][D];
    __shared__ float qq[NW][D];
    __shared__ float redA[4], redB[4];
    const int tid = threadIdx.x;
    const int lane = tid & 31, warp = tid >> 5;

    for (int w = 0; w < NW; w++) {
        float v = query_emb[w * D + tid];
        float s = v, s2 = v * v;
        #pragma unroll
        for (int o = 16; o; o >>= 1) {
            s  += __shfl_down_sync(0xffffffffu, s,  o);
            s2 += __shfl_down_sync(0xffffffffu, s2, o);
        }
        if (lane == 0) { redA[warp] = s; redB[warp] = s2; }
        __syncthreads();
        float m  = (redA[0] + redA[1] + redA[2] + redA[3]) * (1.0f / D);
        float vv = (redB[0] + redB[1] + redB[2] + redB[3]) * (1.0f / D) - m * m;
        float rs = rsqrtf(vv + 1e-5f);
        sq[w][tid] = (v - m) * rs * qg[tid] + qb[tid];
        __syncthreads();
    }
    for (int w = 0; w < NW; w++) {
        float acc = in_proj_b[tid];
        for (int e = 0; e < D; e++) acc += sq[w][e] * in_proj_w[tid * D + e];
        qq[w][tid] = acc;
        g_queries[w][tid] = sq[w][tid];
    }
    __syncthreads();
    for (int h = 0; h < H; h++)
        for (int w = 0; w < NW; w++) {
            float acc = 0.f;
            #pragma unroll
            for (int d = 0; d < 16; d++)
                acc += qq[w][h * 16 + d] * in_proj_w[(D + h * 16 + d) * D + tid];
            g_QWr[h * NW + w][tid] = acc * 0.25f;
        }
    if (tid < R) {
        int h = tid / NW, w = tid % NW;
        float acc = 0.f;
        #pragma unroll
        for (int d = 0; d < 16; d++)
            acc += qq[w][h * 16 + d] * in_proj_b[D + h * 16 + d];
        g_sbias[tid] = acc * 0.25f;
    }
}

// ================= Kernel A: attention -> wt =================
struct SmemA {
    float  tok[NT][132];
    float2 attn2[R][NT];
    float  coords[NT][2];
    float  redA[NT * 4];
    float  redB[NT * 4];
};

__global__ void __launch_bounds__(TPA) attn_kernel(
    const float* __restrict__ track_left,
    const float* __restrict__ track_right,
    const float* __restrict__ coord_w,
    const float* __restrict__ coord_b,
    const float* __restrict__ pos_emb,
    const float* __restrict__ side_emb,
    const float* __restrict__ tok_g,
    const float* __restrict__ tok_b)
{
    __shared__ SmemA S;
    const int tid  = threadIdx.x;
    const int lane = tid & 31;
    const int warp = tid >> 5;

    const float cw0 = coord_w[2 * tid], cw1 = coord_w[2 * tid + 1];
    const float cb  = coord_b[tid];
    const float sd0 = side_emb[tid], sd1 = side_emb[D + tid];
    const float tg  = tok_g[tid],  tbv = tok_b[tid];
    float posr[T10];
    #pragma unroll
    for (int t = 0; t < T10; t++) posr[t] = pos_emb[t * D + tid];

    for (int g = 0; g < GPA; g++) {
        const int b = blockIdx.x * GPA + g;
        __syncthreads();
        if (tid < NT) {
            const float* src = (tid < T10)
                ? (track_left  + (b * T10 + tid) * 2)
                : (track_right + (b * T10 + (tid - T10)) * 2);
            S.coords[tid][0] = src[0];
            S.coords[tid][1] = src[1];
        }
        __syncthreads();

        float pre[NT];
        #pragma unroll
        for (int t = 0; t < NT; t++) {
            float base = cb + posr[(t < T10) ? t : (t - T10)] + ((t < T10) ? sd0 : sd1);
            pre[t] = S.coords[t][0] * cw0 + S.coords[t][1] * cw1 + base;
        }
        #pragma unroll
        for (int t = 0; t < NT; t++) {
            float s = pre[t], s2 = pre[t] * pre[t];
            #pragma unroll
            for (int o = 16; o; o >>= 1) {
                s  += __shfl_down_sync(0xffffffffu, s,  o);
                s2 += __shfl_down_sync(0xffffffffu, s2, o);
            }
            if (lane == 0) { S.redA[t * 4 + warp] = s; S.redB[t * 4 + warp] = s2; }
        }
        __syncthreads();
        #pragma unroll
        for (int t = 0; t < NT; t++) {
            float m  = (S.redA[t*4] + S.redA[t*4+1] + S.redA[t*4+2] + S.redA[t*4+3]) * (1.0f / D);
            float vv = (S.redB[t*4] + S.redB[t*4+1] + S.redB[t*4+2] + S.redB[t*4+3]) * (1.0f / D) - m * m;
            float rs = rsqrtf(vv + 1e-5f);
            S.tok[t][tid] = (pre[t] - m) * rs * tg + tbv;
        }
        __syncthreads();

        // scores[r][t] = sbias[r] + QW[r] . tok[t]
        for (int i = tid; i < R * NT; i += TPA) {
            int r = i / NT, t = i % NT;
            ull acc = 0;
            #pragma unroll 8
            for (int e4 = 0; e4 < 32; e4++) {
                ulonglong2 q  = *reinterpret_cast<const ulonglong2*>(&g_QWr[r][4 * e4]);
                ulonglong2 tt = *reinterpret_cast<const ulonglong2*>(&S.tok[t][4 * e4]);
                ffma2(acc, q.x, tt.x);
                ffma2(acc, q.y, tt.y);
            }
            S.attn2[r][t].x = foldp(acc) + g_sbias[r];
        }
        __syncthreads();

        if (tid < R) {
            float mx = -1e30f;
            #pragma unroll
            for (int t = 0; t < NT; t++) mx = fmaxf(mx, S.attn2[tid][t].x);
            float ex[NT], sum = 0.f;
            #pragma unroll
            for (int t = 0; t < NT; t++) { ex[t] = expf(S.attn2[tid][t].x - mx); sum += ex[t]; }
            float inv = 1.0f / sum;
            #pragma unroll
            for (int t = 0; t < NT; t++) {
                float a = ex[t] * inv;
                S.attn2[tid][t] = make_float2(a, a);
            }
        }
        __syncthreads();

        // wt[r][:] = attn[r] @ tok  -> global  (warp -> rows warp+4j, lane -> 4 dims)
        {
            ull acc[6][2] = {};
            #pragma unroll
            for (int t = 0; t < NT; t++) {
                ulonglong2 tp = *reinterpret_cast<const ulonglong2*>(&S.tok[t][lane * 4]);
                #pragma unroll
                for (int j = 0; j < 6; j++) {
                    ull a = *reinterpret_cast<const ull*>(&S.attn2[warp + 4 * j][t]);
                    ffma2(acc[j][0], a, tp.x);
                    ffma2(acc[j][1], a, tp.y);
                }
            }
            #pragma unroll
            for (int j = 0; j < 6; j++) {
                ulonglong2 v; v.x = acc[j][0]; v.y = acc[j][1];
                *reinterpret_cast<ulonglong2*>(&g_wt[b][warp + 4 * j][lane * 4]) = v;
            }
        }
    }
}

// ================= Kernel B: ctx / out_proj / LN / FFN / LN / head =================
// smem pool layout (bytes):
//   [0,       131072)  wbuf  : staged weights (float2), up to 128 KB
//   [131072,  155648)  X     : x[NB][3][128]
//   [155648,  204800)  Hb    : h[NB][3][256]  (ctx[NB][3][128] aliases its first 24 KB)
//   [204800,  229376)  Y     : raw GEMM outputs [NB][3][128]
#define SMEMB_BYTES 229376

__global__ void __launch_bounds__(TPB, 1) ffn_kernel(
    const float* __restrict__ in_proj_b,
    const float* __restrict__ out_proj_b,
    const float* __restrict__ fc1_b,
    const float* __restrict__ fc2_b,
    const float* __restrict__ pa_g, const float* __restrict__ pa_b,
    const float* __restrict__ pf_g, const float* __restrict__ pf_b,
    const float* __restrict__ head_w, const float* __restrict__ head_b,
    float* __restrict__ out)
{
    extern __shared__ char smemB[];
    float2* wbuf = reinterpret_cast<float2*>(smemB);
    float*  X    = reinterpret_cast<float*>(smemB + 131072);
    float*  Hb   = reinterpret_cast<float*>(smemB + 155648);
    float*  Y    = reinterpret_cast<float*>(smemB + 204800);

    const int tid  = threadIdx.x;
    const int lane = tid & 31;
    const int warp = tid >> 5;
    const int bp   = warp >> 1;        // batch pair 0..7
    const int ch   = warp & 1;         // column half
    const int b0   = 2 * bp;           // local batch base
    const int c    = ch * 64 + lane * 2;   // output col pair base (0..126)
    const int bg0  = blockIdx.x * NB;

    #define XI(b,w)  (X  + ((b) * 3 + (w)) * 128)
    #define HIX(b,w) (Hb + ((b) * 3 + (w)) * 256)
    #define CIX(b,w) (Hb + ((b) * 3 + (w)) * 128)
    #define YI(b,w)  (Y  + ((b) * 3 + (w)) * 128)

    // ---- stage wv (64 KB) ----
    {
        const float4* s = reinterpret_cast<const float4*>(g_wv_p);
        float4* d = reinterpret_cast<float4*>(wbuf);
        for (int i = tid; i < 4096; i += TPB) d[i] = s[i];
    }
    __syncthreads();

    // ---- ctx = wt @ wv + bv ----
    {
        const int hh = c >> 4;      // head for this col pair
        ull acc[2][3][2] = {};
        const float* wt0 = &g_wt[bg0 + b0][0][0];
        const float* wt1 = &g_wt[bg0 + b0 + 1][0][0];
        #pragma unroll 4
        for (int s = 0; s < 32; s++) {
            int k2 = 2 * s;
            ulonglong2 w0 = *reinterpret_cast<const ulonglong2*>(&wbuf[k2 * 128 + c]);
            ulonglong2 w1 = *reinterpret_cast<const ulonglong2*>(&wbuf[(k2 + 1) * 128 + c]);
            #pragma unroll
            for (int w = 0; w < 3; w++) {
                ulonglong2 a0 = *reinterpret_cast<const ulonglong2*>(wt0 + (hh * 3 + w) * D + 2 * k2);
                ulonglong2 a1 = *reinterpret_cast<const ulonglong2*>(wt1 + (hh * 3 + w) * D + 2 * k2);
                ffma2(acc[0][w][0], a0.x, w0.x); ffma2(acc[0][w][1], a0.x, w0.y);
                ffma2(acc[0][w][0], a0.y, w1.x); ffma2(acc[0][w][1], a0.y, w1.y);
                ffma2(acc[1][w][0], a1.x, w0.x); ffma2(acc[1][w][1], a1.x, w0.y);
                ffma2(acc[1][w][0], a1.y, w1.x); ffma2(acc[1][w][1], a1.y, w1.y);
            }
        }
        const float* bvp = in_proj_b + 2 * D;
        float bv0 = bvp[c], bv1 = bvp[c + 1];
        #pragma unroll
        for (int bb = 0; bb < 2; bb++)
            #pragma unroll
            for (int w = 0; w < 3; w++)
                *reinterpret_cast<float2*>(CIX(b0 + bb, w) + c) =
                    make_float2(foldp(acc[bb][w][0]) + bv0, foldp(acc[bb][w][1]) + bv1);
    }
    __syncthreads();

    // ---- stage op (64 KB) ----
    {
        const float4* s = reinterpret_cast<const float4*>(g_op_p);
        float4* d = reinterpret_cast<float4*>(wbuf);
        for (int i = tid; i < 4096; i += TPB) d[i] = s[i];
    }
    __syncthreads();

    // ---- attn_out(raw) = ctx @ op ----
    {
        ull acc[2][3][2] = {};
        #pragma unroll 4
        for (int s = 0; s < 32; s++) {
            int k2 = 2 * s;
            ulonglong2 w0 = *reinterpret_cast<const ulonglong2*>(&wbuf[k2 * 128 + c]);
            ulonglong2 w1 = *reinterpret_cast<const ulonglong2*>(&wbuf[(k2 + 1) * 128 + c]);
            #pragma unroll
            for (int bb = 0; bb < 2; bb++)
                #pragma unroll
                for (int w = 0; w < 3; w++) {
                    ulonglong2 a = *reinterpret_cast<const ulonglong2*>(CIX(b0 + bb, w) + 2 * k2);
                    ffma2(acc[bb][w][0], a.x, w0.x); ffma2(acc[bb][w][1], a.x, w0.y);
                    ffma2(acc[bb][w][0], a.y, w1.x); ffma2(acc[bb][w][1], a.y, w1.y);
                }
        }
        #pragma unroll
        for (int bb = 0; bb < 2; bb++)
            #pragma unroll
            for (int w = 0; w < 3; w++)
                *reinterpret_cast<float2*>(YI(b0 + bb, w) + c) =
                    make_float2(foldp(acc[bb][w][0]), foldp(acc[bb][w][1]));
    }
    __syncthreads();

    // ---- LN1: x = LN(queries + attn_out + ob) ----  (warp <-> batch)
    {
        const int b = warp;
        const int c4 = lane * 4;
        float4 ob  = *reinterpret_cast<const float4*>(&out_proj_b[c4]);
        float4 gg  = *reinterpret_cast<const float4*>(&pa_g[c4]);
        float4 bb4 = *reinterpret_cast<const float4*>(&pa_b[c4]);
        #pragma unroll
        for (int w = 0; w < 3; w++) {
            float4 v = *reinterpret_cast<float4*>(YI(b, w) + c4);
            float4 q = *reinterpret_cast<const float4*>(&g_queries[w][c4]);
            float val0 = v.x + ob.x + q.x, val1 = v.y + ob.y + q.y;
            float val2 = v.z + ob.z + q.z, val3 = v.w + ob.w + q.w;
            float s  = val0 + val1 + val2 + val3;
            float s2 = val0*val0 + val1*val1 + val2*val2 + val3*val3;
            #pragma unroll
            for (int o = 16; o; o >>= 1) {
                s  += __shfl_xor_sync(0xffffffffu, s,  o);
                s2 += __shfl_xor_sync(0xffffffffu, s2, o);
            }
            float m  = s * (1.0f / D);
            float vv = s2 * (1.0f / D) - m * m;
            float rs = rsqrtf(vv + 1e-5f);
            *reinterpret_cast<float4*>(XI(b, w) + c4) =
                make_float4((val0 - m) * rs * gg.x + bb4.x, (val1 - m) * rs * gg.y + bb4.y,
                            (val2 - m) * rs * gg.z + bb4.z, (val3 - m) * rs * gg.w + bb4.w);
        }
    }
    __syncthreads();

    // ---- stage fc1 (128 KB) ----
    {
        const float4* s = reinterpret_cast<const float4*>(g_fc1_p);
        float4* d = reinterpret_cast<float4*>(wbuf);
        for (int i = tid; i < 8192; i += TPB) d[i] = s[i];
    }
    __syncthreads();

    // ---- h = relu(x @ fc1 + b) ----  (writes over ctx alias; ctx is dead)
    #pragma unroll
    for (int p = 0; p < 2; p++) {
        ull acc[2][3][2] = {};
        #pragma unroll 4
        for (int s = 0; s < 32; s++) {
            int k2 = 2 * s;
            ulonglong2 w0 = *reinterpret_cast<const ulonglong2*>(&wbuf[k2 * 256 + p * 128 + c]);
            ulonglong2 w1 = *reinterpret_cast<const ulonglong2*>(&wbuf[(k2 + 1) * 256 + p * 128 + c]);
            #pragma unroll
            for (int bb = 0; bb < 2; bb++)
                #pragma unroll
                for (int w = 0; w < 3; w++) {
                    ulonglong2 a = *reinterpret_cast<const ulonglong2*>(XI(b0 + bb, w) + 2 * k2);
                    ffma2(acc[bb][w][0], a.x, w0.x); ffma2(acc[bb][w][1], a.x, w0.y);
                    ffma2(acc[bb][w][0], a.y, w1.x); ffma2(acc[bb][w][1], a.y, w1.y);
                }
        }
        float fb0 = fc1_b[p * 128 + c], fb1 = fc1_b[p * 128 + c + 1];
        #pragma unroll
        for (int bb = 0; bb < 2; bb++)
            #pragma unroll
            for (int w = 0; w < 3; w++)
                *reinterpret_cast<float2*>(HIX(b0 + bb, w) + p * 128 + c) =
                    make_float2(fmaxf(foldp(acc[bb][w][0]) + fb0, 0.f),
                                fmaxf(foldp(acc[bb][w][1]) + fb1, 0.f));
        if (p == 0) __syncthreads();   // keep wbuf reads coherent? (no: wbuf unchanged) -- barrier only to
                                       // even out progress; harmless and cheap
    }
    __syncthreads();

    // ---- stage fc2 (128 KB) ----
    {
        const float4* s = reinterpret_cast<const float4*>(g_fc2_p);
        float4* d = reinterpret_cast<float4*>(wbuf);
        for (int i = tid; i < 8192; i += TPB) d[i] = s[i];
    }
    __syncthreads();

    // ---- y(raw) = h @ fc2 ----
    {
        ull acc[2][3][2] = {};
        #pragma unroll 4
        for (int s = 0; s < 64; s++) {
            int k2 = 2 * s;
            ulonglong2 w0 = *reinterpret_cast<const ulonglong2*>(&wbuf[k2 * 128 + c]);
            ulonglong2 w1 = *reinterpret_cast<const ulonglong2*>(&wbuf[(k2 + 1) * 128 + c]);
            #pragma unroll
            for (int bb = 0; bb < 2; bb++)
                #pragma unroll
                for (int w = 0; w < 3; w++) {
                    ulonglong2 a = *reinterpret_cast<const ulonglong2*>(HIX(b0 + bb, w) + 2 * k2);
                    ffma2(acc[bb][w][0], a.x, w0.x); ffma2(acc[bb][w][1], a.x, w0.y);
                    ffma2(acc[bb][w][0], a.y, w1.x); ffma2(acc[bb][w][1], a.y, w1.y);
                }
        }
        #pragma unroll
        for (int bb = 0; bb < 2; bb++)
            #pragma unroll
            for (int w = 0; w < 3; w++)
                *reinterpret_cast<float2*>(YI(b0 + bb, w) + c) =
                    make_float2(foldp(acc[bb][w][0]), foldp(acc[bb][w][1]));
    }
    __syncthreads();

    // ---- LN2 + head ----  (warp <-> batch)
    {
        const int b = warp;
        const int c4 = lane * 4;
        float4 fb  = *reinterpret_cast<const float4*>(&fc2_b[c4]);
        float4 gg  = *reinterpret_cast<const float4*>(&pf_g[c4]);
        float4 bb4 = *reinterpret_cast<const float4*>(&pf_b[c4]);
        float4 hw0 = *reinterpret_cast<const float4*>(&head_w[c4]);
        float4 hw1 = *reinterpret_cast<const float4*>(&head_w[D + c4]);
        const float hb0 = head_b[0], hb1 = head_b[1];
        #pragma unroll
        for (int w = 0; w < 3; w++) {
            float4 v = *reinterpret_cast<float4*>(YI(b, w) + c4);
            float4 xr = *reinterpret_cast<float4*>(XI(b, w) + c4);
            float val0 = v.x + fb.x + xr.x, val1 = v.y + fb.y + xr.y;
            float val2 = v.z + fb.z + xr.z, val3 = v.w + fb.w + xr.w;
            float s  = val0 + val1 + val2 + val3;
            float s2 = val0*val0 + val1*val1 + val2*val2 + val3*val3;
            #pragma unroll
            for (int o = 16; o; o >>= 1) {
                s  += __shfl_xor_sync(0xffffffffu, s,  o);
                s2 += __shfl_xor_sync(0xffffffffu, s2, o);
            }
            float m  = s * (1.0f / D);
            float vv = s2 * (1.0f / D) - m * m;
            float rs = rsqrtf(vv + 1e-5f);
            float x0 = (val0 - m) * rs * gg.x + bb4.x;
            float x1 = (val1 - m) * rs * gg.y + bb4.y;
            float x2 = (val2 - m) * rs * gg.z + bb4.z;
            float x3 = (val3 - m) * rs * gg.w + bb4.w;
            float d0 = x0 * hw0.x + x1 * hw0.y + x2 * hw0.z + x3 * hw0.w;
            float d1 = x0 * hw1.x + x1 * hw1.y + x2 * hw1.z + x3 * hw1.w;
            #pragma unroll
            for (int o = 16; o; o >>= 1) {
                d0 += __shfl_xor_sync(0xffffffffu, d0, o);
                d1 += __shfl_xor_sync(0xffffffffu, d1, o);
            }
            if (lane == 0) {
                out[(bg0 + b) * 6 + w * 2 + 0] = d0 + hb0;
                out[(bg0 + b) * 6 + w * 2 + 1] = d1 + hb1;
            }
        }
    }
}

// ---------------- launch ----------------
extern "C" void kernel_launch(void* const* d_in, const int* in_sizes, int n_in,
                              void* d_out, int out_size)
{
    const float* track_left   = (const float*)d_in[0];
    const float* track_right  = (const float*)d_in[1];
    const float* coord_w      = (const float*)d_in[2];
    const float* coord_b      = (const float*)d_in[3];
    const float* pos_emb      = (const float*)d_in[4];
    const float* side_emb     = (const float*)d_in[5];
    const float* query_emb    = (const float*)d_in[6];
    const float* tokens_ln_g  = (const float*)d_in[7];
    const float* tokens_ln_b  = (const float*)d_in[8];
    const float* queries_ln_g = (const float*)d_in[9];
    const float* queries_ln_b = (const float*)d_in[10];
    const float* in_proj_w    = (const float*)d_in[11];
    const float* in_proj_b    = (const float*)d_in[12];
    const float* out_proj_w   = (const float*)d_in[13];
    const float* out_proj_b   = (const float*)d_in[14];
    const float* fc1_w        = (const float*)d_in[15];
    const float* fc1_b        = (const float*)d_in[16];
    const float* fc2_w        = (const float*)d_in[17];
    const float* fc2_b        = (const float*)d_in[18];
    const float* pa_g         = (const float*)d_in[19];
    const float* pa_b         = (const float*)d_in[20];
    const float* pf_g         = (const float*)d_in[21];
    const float* pf_b         = (const float*)d_in[22];
    const float* head_w       = (const float*)d_in[23];
    const float* head_b       = (const float*)d_in[24];
    float* out = (float*)d_out;

    const int nb = in_sizes[0] / (T10 * 2);   // 32768

    prep_weights<<<96, 256>>>(in_proj_w, out_proj_w, fc1_w, fc2_w);
    precompute_kernel<<<1, 128>>>(query_emb, queries_ln_g, queries_ln_b, in_proj_w, in_proj_b);

    attn_kernel<<<nb / GPA, TPA>>>(track_left, track_right, coord_w, coord_b,
                                   pos_emb, side_emb, tokens_ln_g, tokens_ln_b);

    cudaFuncSetAttribute(ffn_kernel, cudaFuncAttributeMaxDynamicSharedMemorySize, SMEMB_BYTES);
    ffn_kernel<<<nb / NB, TPB, SMEMB_BYTES>>>(in_proj_b, out_proj_b, fc1_b, fc2_b,
                                              pa_g, pa_b, pf_g, pf_b, head_w, head_b, out);
}

// round 10
// speedup vs baseline: 1.0018x; 1.0018x over previous
#include <cuda_runtime.h>

typedef unsigned long long ull;

#define T10 10
#define NT  20
#define NW  3
#define D   128
#define H   8
#define R   24        // H*NW
#define NBATCH 32768
#define TPA 128       // attn kernel threads
#define GPA 2         // batches per attn CTA
#define TPB 512       // ffn kernel threads (16 warps)
#define NB  16        // batches per ffn CTA

// ---------------- device scratch ----------------
__device__ __align__(16) float g_QWr[R][D];
__device__ float g_sbias[R];
__device__ __align__(16) float g_queries[NW][D];
// pair-interleaved weights over reduction dim k: (k2, n) = (W_t[2k2][n], W_t[2k2+1][n])
__device__ __align__(16) float2 g_wv_p[64][128];
__device__ __align__(16) float2 g_op_p[64][128];
__device__ __align__(16) float2 g_fc1_p[64][256];
__device__ __align__(16) float2 g_fc2_p[128][128];
// attention-weighted tokens (intermediate), 402 MB scratch
__device__ __align__(16) float g_wt[NBATCH][R][D];

// ---------------- f32x2 helpers ----------------
__device__ __forceinline__ void ffma2(ull& d, ull a, ull b) {
    asm("fma.rn.f32x2 %0, %1, %2, %0;" : "+l"(d) : "l"(a), "l"(b));
}
__device__ __forceinline__ float foldp(ull v) {
    float2 f = *reinterpret_cast<float2*>(&v);
    return f.x + f.y;
}

// ---------------- weight prep ----------------
__global__ void prep_weights(const float* __restrict__ in_proj_w,
                             const float* __restrict__ out_proj_w,
                             const float* __restrict__ fc1_w,
                             const float* __restrict__ fc2_w)
{
    int idx = blockIdx.x * blockDim.x + threadIdx.x;
    int stride = gridDim.x * blockDim.x;
    for (int i = idx; i < 64 * 128; i += stride) {
        int k2 = i >> 7, n = i & 127;
        g_wv_p[k2][n] = make_float2(in_proj_w[(2 * D + n) * D + 2 * k2],
                                    in_proj_w[(2 * D + n) * D + 2 * k2 + 1]);
        g_op_p[k2][n] = make_float2(out_proj_w[n * D + 2 * k2],
                                    out_proj_w[n * D + 2 * k2 + 1]);
    }
    for (int i = idx; i < 64 * 256; i += stride) {
        int k2 = i >> 8, n = i & 255;
        g_fc1_p[k2][n] = make_float2(fc1_w[n * D + 2 * k2], fc1_w[n * D + 2 * k2 + 1]);
    }
    for (int i = idx; i < 128 * 128; i += stride) {
        int k2 = i >> 7, n = i & 127;
        g_fc2_p[k2][n] = make_float2(fc2_w[n * 2 * D + 2 * k2], fc2_w[n * 2 * D + 2 * k2 + 1]);
    }
}

// ---------------- precompute: query LN, q, QW, score bias ----------------
__global__ void precompute_kernel(const float* __restrict__ query_emb,
                                  const float* __restrict__ qg,
                                  const float* __restrict__ qb,
                                  const float* __restrict__ in_proj_w,
                                  const float* __restrict__ in_proj_b)
{
    __shared__ float sq[NW][D];
    __shared__ float qq[NW][D];
    __shared__ float redA[4], redB[4];
    const int tid = threadIdx.x;
    const int lane = tid & 31, warp = tid >> 5;

    for (int w = 0; w < NW; w++) {
        float v = query_emb[w * D + tid];
        float s = v, s2 = v * v;
        #pragma unroll
        for (int o = 16; o; o >>= 1) {
            s  += __shfl_down_sync(0xffffffffu, s,  o);
            s2 += __shfl_down_sync(0xffffffffu, s2, o);
        }
        if (lane == 0) { redA[warp] = s; redB[warp] = s2; }
        __syncthreads();
        float m  = (redA[0] + redA[1] + redA[2] + redA[3]) * (1.0f / D);
        float vv = (redB[0] + redB[1] + redB[2] + redB[3]) * (1.0f / D) - m * m;
        float rs = rsqrtf(vv + 1e-5f);
        sq[w][tid] = (v - m) * rs * qg[tid] + qb[tid];
        __syncthreads();
    }
    for (int w = 0; w < NW; w++) {
        float acc = in_proj_b[tid];
        for (int e = 0; e < D; e++) acc += sq[w][e] * in_proj_w[tid * D + e];
        qq[w][tid] = acc;
        g_queries[w][tid] = sq[w][tid];
    }
    __syncthreads();
    for (int h = 0; h < H; h++)
        for (int w = 0; w < NW; w++) {
            float acc = 0.f;
            #pragma unroll
            for (int d = 0; d < 16; d++)
                acc += qq[w][h * 16 + d] * in_proj_w[(D + h * 16 + d) * D + tid];
            g_QWr[h * NW + w][tid] = acc * 0.25f;
        }
    if (tid < R) {
        int h = tid / NW, w = tid % NW;
        float acc = 0.f;
        #pragma unroll
        for (int d = 0; d < 16; d++)
            acc += qq[w][h * 16 + d] * in_proj_b[D + h * 16 + d];
        g_sbias[tid] = acc * 0.25f;
    }
}

// ================= Kernel A: attention -> wt =================
struct SmemA {
    float  tok[NT][132];
    float2 attn2[R][NT];
    float  coords[NT][2];
    float  redA[NT * 4];
    float  redB[NT * 4];
};

__global__ void __launch_bounds__(TPA) attn_kernel(
    const float* __restrict__ track_left,
    const float* __restrict__ track_right,
    const float* __restrict__ coord_w,
    const float* __restrict__ coord_b,
    const float* __restrict__ pos_emb,
    const float* __restrict__ side_emb,
    const float* __restrict__ tok_g,
    const float* __restrict__ tok_b)
{
    __shared__ SmemA S;
    const int tid  = threadIdx.x;
    const int lane = tid & 31;
    const int warp = tid >> 5;

    const float cw0 = coord_w[2 * tid], cw1 = coord_w[2 * tid + 1];
    const float cb  = coord_b[tid];
    const float sd0 = side_emb[tid], sd1 = side_emb[D + tid];
    const float tg  = tok_g[tid],  tbv = tok_b[tid];
    float posr[T10];
    #pragma unroll
    for (int t = 0; t < T10; t++) posr[t] = pos_emb[t * D + tid];

    for (int g = 0; g < GPA; g++) {
        const int b = blockIdx.x * GPA + g;
        __syncthreads();
        if (tid < NT) {
            const float* src = (tid < T10)
                ? (track_left  + (b * T10 + tid) * 2)
                : (track_right + (b * T10 + (tid - T10)) * 2);
            S.coords[tid][0] = src[0];
            S.coords[tid][1] = src[1];
        }
        __syncthreads();

        float pre[NT];
        #pragma unroll
        for (int t = 0; t < NT; t++) {
            float base = cb + posr[(t < T10) ? t : (t - T10)] + ((t < T10) ? sd0 : sd1);
            pre[t] = S.coords[t][0] * cw0 + S.coords[t][1] * cw1 + base;
        }
        #pragma unroll
        for (int t = 0; t < NT; t++) {
            float s = pre[t], s2 = pre[t] * pre[t];
            #pragma unroll
            for (int o = 16; o; o >>= 1) {
                s  += __shfl_down_sync(0xffffffffu, s,  o);
                s2 += __shfl_down_sync(0xffffffffu, s2, o);
            }
            if (lane == 0) { S.redA[t * 4 + warp] = s; S.redB[t * 4 + warp] = s2; }
        }
        __syncthreads();
        #pragma unroll
        for (int t = 0; t < NT; t++) {
            float m  = (S.redA[t*4] + S.redA[t*4+1] + S.redA[t*4+2] + S.redA[t*4+3]) * (1.0f / D);
            float vv = (S.redB[t*4] + S.redB[t*4+1] + S.redB[t*4+2] + S.redB[t*4+3]) * (1.0f / D) - m * m;
            float rs = rsqrtf(vv + 1e-5f);
            S.tok[t][tid] = (pre[t] - m) * rs * tg + tbv;
        }
        __syncthreads();

        // scores[r][t] = sbias[r] + QW[r] . tok[t]
        for (int i = tid; i < R * NT; i += TPA) {
            int r = i / NT, t = i % NT;
            ull acc = 0;
            #pragma unroll 8
            for (int e4 = 0; e4 < 32; e4++) {
                ulonglong2 q  = *reinterpret_cast<const ulonglong2*>(&g_QWr[r][4 * e4]);
                ulonglong2 tt = *reinterpret_cast<const ulonglong2*>(&S.tok[t][4 * e4]);
                ffma2(acc, q.x, tt.x);
                ffma2(acc, q.y, tt.y);
            }
            S.attn2[r][t].x = foldp(acc) + g_sbias[r];
        }
        __syncthreads();

        if (tid < R) {
            float mx = -1e30f;
            #pragma unroll
            for (int t = 0; t < NT; t++) mx = fmaxf(mx, S.attn2[tid][t].x);
            float ex[NT], sum = 0.f;
            #pragma unroll
            for (int t = 0; t < NT; t++) { ex[t] = expf(S.attn2[tid][t].x - mx); sum += ex[t]; }
            float inv = 1.0f / sum;
            #pragma unroll
            for (int t = 0; t < NT; t++) {
                float a = ex[t] * inv;
                S.attn2[tid][t] = make_float2(a, a);
            }
        }
        __syncthreads();

        // wt[r][:] = attn[r] @ tok  -> global  (warp -> rows warp+4j, lane -> 4 dims)
        {
            ull acc[6][2] = {};
            #pragma unroll
            for (int t = 0; t < NT; t++) {
                ulonglong2 tp = *reinterpret_cast<const ulonglong2*>(&S.tok[t][lane * 4]);
                #pragma unroll
                for (int j = 0; j < 6; j++) {
                    ull a = *reinterpret_cast<const ull*>(&S.attn2[warp + 4 * j][t]);
                    ffma2(acc[j][0], a, tp.x);
                    ffma2(acc[j][1], a, tp.y);
                }
            }
            #pragma unroll
            for (int j = 0; j < 6; j++) {
                ulonglong2 v; v.x = acc[j][0]; v.y = acc[j][1];
                *reinterpret_cast<ulonglong2*>(&g_wt[b][warp + 4 * j][lane * 4]) = v;
            }
        }
    }
}

// ================= Kernel B: ctx / out_proj / LN / FFN / LN / head =================
// smem pool layout (bytes):
//   [0,       131072)  wbuf  : staged weights (float2), up to 128 KB
//   [131072,  155648)  X     : x[NB][3][128]
//   [155648,  204800)  Hb    : h[NB][3][256]  (ctx[NB][3][128] aliases its first 24 KB)
//   [204800,  229376)  Y     : raw GEMM outputs [NB][3][128]
#define SMEMB_BYTES 229376

__global__ void __launch_bounds__(TPB, 1) ffn_kernel(
    const float* __restrict__ in_proj_b,
    const float* __restrict__ out_proj_b,
    const float* __restrict__ fc1_b,
    const float* __restrict__ fc2_b,
    const float* __restrict__ pa_g, const float* __restrict__ pa_b,
    const float* __restrict__ pf_g, const float* __restrict__ pf_b,
    const float* __restrict__ head_w, const float* __restrict__ head_b,
    float* __restrict__ out)
{
    extern __shared__ char smemB[];
    float2* wbuf = reinterpret_cast<float2*>(smemB);
    float*  X    = reinterpret_cast<float*>(smemB + 131072);
    float*  Hb   = reinterpret_cast<float*>(smemB + 155648);
    float*  Y    = reinterpret_cast<float*>(smemB + 204800);

    const int tid  = threadIdx.x;
    const int lane = tid & 31;
    const int warp = tid >> 5;
    const int bp   = warp >> 1;        // batch pair 0..7
    const int ch   = warp & 1;         // column half
    const int b0   = 2 * bp;           // local batch base
    const int c    = ch * 64 + lane * 2;   // output col pair base (0..126)
    const int bg0  = blockIdx.x * NB;

    #define XI(b,w)  (X  + ((b) * 3 + (w)) * 128)
    #define HIX(b,w) (Hb + ((b) * 3 + (w)) * 256)
    #define CIX(b,w) (Hb + ((b) * 3 + (w)) * 128)
    #define YI(b,w)  (Y  + ((b) * 3 + (w)) * 128)

    // ---- stage wv (64 KB) ----
    {
        const float4* s = reinterpret_cast<const float4*>(g_wv_p);
        float4* d = reinterpret_cast<float4*>(wbuf);
        for (int i = tid; i < 4096; i += TPB) d[i] = s[i];
    }
    __syncthreads();

    // ---- ctx = wt @ wv + bv ----
    {
        const int hh = c >> 4;      // head for this col pair
        ull acc[2][3][2] = {};
        const float* wt0 = &g_wt[bg0 + b0][0][0];
        const float* wt1 = &g_wt[bg0 + b0 + 1][0][0];
        #pragma unroll 4
        for (int s = 0; s < 32; s++) {
            int k2 = 2 * s;
            ulonglong2 w0 = *reinterpret_cast<const ulonglong2*>(&wbuf[k2 * 128 + c]);
            ulonglong2 w1 = *reinterpret_cast<const ulonglong2*>(&wbuf[(k2 + 1) * 128 + c]);
            #pragma unroll
            for (int w = 0; w < 3; w++) {
                ulonglong2 a0 = *reinterpret_cast<const ulonglong2*>(wt0 + (hh * 3 + w) * D + 2 * k2);
                ulonglong2 a1 = *reinterpret_cast<const ulonglong2*>(wt1 + (hh * 3 + w) * D + 2 * k2);
                ffma2(acc[0][w][0], a0.x, w0.x); ffma2(acc[0][w][1], a0.x, w0.y);
                ffma2(acc[0][w][0], a0.y, w1.x); ffma2(acc[0][w][1], a0.y, w1.y);
                ffma2(acc[1][w][0], a1.x, w0.x); ffma2(acc[1][w][1], a1.x, w0.y);
                ffma2(acc[1][w][0], a1.y, w1.x); ffma2(acc[1][w][1], a1.y, w1.y);
            }
        }
        const float* bvp = in_proj_b + 2 * D;
        float bv0 = bvp[c], bv1 = bvp[c + 1];
        #pragma unroll
        for (int bb = 0; bb < 2; bb++)
            #pragma unroll
            for (int w = 0; w < 3; w++)
                *reinterpret_cast<float2*>(CIX(b0 + bb, w) + c) =
                    make_float2(foldp(acc[bb][w][0]) + bv0, foldp(acc[bb][w][1]) + bv1);
    }
    __syncthreads();

    // ---- stage op (64 KB) ----
    {
        const float4* s = reinterpret_cast<const float4*>(g_op_p);
        float4* d = reinterpret_cast<float4*>(wbuf);
        for (int i = tid; i < 4096; i += TPB) d[i] = s[i];
    }
    __syncthreads();

    // ---- attn_out(raw) = ctx @ op ----
    {
        ull acc[2][3][2] = {};
        #pragma unroll 4
        for (int s = 0; s < 32; s++) {
            int k2 = 2 * s;
            ulonglong2 w0 = *reinterpret_cast<const ulonglong2*>(&wbuf[k2 * 128 + c]);
            ulonglong2 w1 = *reinterpret_cast<const ulonglong2*>(&wbuf[(k2 + 1) * 128 + c]);
            #pragma unroll
            for (int bb = 0; bb < 2; bb++)
                #pragma unroll
                for (int w = 0; w < 3; w++) {
                    ulonglong2 a = *reinterpret_cast<const ulonglong2*>(CIX(b0 + bb, w) + 2 * k2);
                    ffma2(acc[bb][w][0], a.x, w0.x); ffma2(acc[bb][w][1], a.x, w0.y);
                    ffma2(acc[bb][w][0], a.y, w1.x); ffma2(acc[bb][w][1], a.y, w1.y);
                }
        }
        #pragma unroll
        for (int bb = 0; bb < 2; bb++)
            #pragma unroll
            for (int w = 0; w < 3; w++)
                *reinterpret_cast<float2*>(YI(b0 + bb, w) + c) =
                    make_float2(foldp(acc[bb][w][0]), foldp(acc[bb][w][1]));
    }
    __syncthreads();

    // ---- LN1: x = LN(queries + attn_out + ob) ----  (warp <-> batch)
    {
        const int b = warp;
        const int c4 = lane * 4;
        float4 ob  = *reinterpret_cast<const float4*>(&out_proj_b[c4]);
        float4 gg  = *reinterpret_cast<const float4*>(&pa_g[c4]);
        float4 bb4 = *reinterpret_cast<const float4*>(&pa_b[c4]);
        #pragma unroll
        for (int w = 0; w < 3; w++) {
            float4 v = *reinterpret_cast<float4*>(YI(b, w) + c4);
            float4 q = *reinterpret_cast<const float4*>(&g_queries[w][c4]);
            float val0 = v.x + ob.x + q.x, val1 = v.y + ob.y + q.y;
            float val2 = v.z + ob.z + q.z, val3 = v.w + ob.w + q.w;
            float s  = val0 + val1 + val2 + val3;
            float s2 = val0*val0 + val1*val1 + val2*val2 + val3*val3;
            #pragma unroll
            for (int o = 16; o; o >>= 1) {
                s  += __shfl_xor_sync(0xffffffffu, s,  o);
                s2 += __shfl_xor_sync(0xffffffffu, s2, o);
            }
            float m  = s * (1.0f / D);
            float vv = s2 * (1.0f / D) - m * m;
            float rs = rsqrtf(vv + 1e-5f);
            *reinterpret_cast<float4*>(XI(b, w) + c4) =
                make_float4((val0 - m) * rs * gg.x + bb4.x, (val1 - m) * rs * gg.y + bb4.y,
                            (val2 - m) * rs * gg.z + bb4.z, (val3 - m) * rs * gg.w + bb4.w);
        }
    }
    __syncthreads();

    // ---- stage fc1 (128 KB) ----
    {
        const float4* s = reinterpret_cast<const float4*>(g_fc1_p);
        float4* d = reinterpret_cast<float4*>(wbuf);
        for (int i = tid; i < 8192; i += TPB) d[i] = s[i];
    }
    __syncthreads();

    // ---- h = relu(x @ fc1 + b) ----  (writes over ctx alias; ctx is dead)
    #pragma unroll
    for (int p = 0; p < 2; p++) {
        ull acc[2][3][2] = {};
        #pragma unroll 4
        for (int s = 0; s < 32; s++) {
            int k2 = 2 * s;
            ulonglong2 w0 = *reinterpret_cast<const ulonglong2*>(&wbuf[k2 * 256 + p * 128 + c]);
            ulonglong2 w1 = *reinterpret_cast<const ulonglong2*>(&wbuf[(k2 + 1) * 256 + p * 128 + c]);
            #pragma unroll
            for (int bb = 0; bb < 2; bb++)
                #pragma unroll
                for (int w = 0; w < 3; w++) {
                    ulonglong2 a = *reinterpret_cast<const ulonglong2*>(XI(b0 + bb, w) + 2 * k2);
                    ffma2(acc[bb][w][0], a.x, w0.x); ffma2(acc[bb][w][1], a.x, w0.y);
                    ffma2(acc[bb][w][0], a.y, w1.x); ffma2(acc[bb][w][1], a.y, w1.y);
                }
        }
        float fb0 = fc1_b[p * 128 + c], fb1 = fc1_b[p * 128 + c + 1];
        #pragma unroll
        for (int bb = 0; bb < 2; bb++)
            #pragma unroll
            for (int w = 0; w < 3; w++)
                *reinterpret_cast<float2*>(HIX(b0 + bb, w) + p * 128 + c) =
                    make_float2(fmaxf(foldp(acc[bb][w][0]) + fb0, 0.f),
                                fmaxf(foldp(acc[bb][w][1]) + fb1, 0.f));
        if (p == 0) __syncthreads();   // keep wbuf reads coherent? (no: wbuf unchanged) -- barrier only to
                                       // even out progress; harmless and cheap
    }
    __syncthreads();

    // ---- stage fc2 (128 KB) ----
    {
        const float4* s = reinterpret_cast<const float4*>(g_fc2_p);
        float4* d = reinterpret_cast<float4*>(wbuf);
        for (int i = tid; i < 8192; i += TPB) d[i] = s[i];
    }
    __syncthreads();

    // ---- y(raw) = h @ fc2 ----
    {
        ull acc[2][3][2] = {};
        #pragma unroll 4
        for (int s = 0; s < 64; s++) {
            int k2 = 2 * s;
            ulonglong2 w0 = *reinterpret_cast<const ulonglong2*>(&wbuf[k2 * 128 + c]);
            ulonglong2 w1 = *reinterpret_cast<const ulonglong2*>(&wbuf[(k2 + 1) * 128 + c]);
            #pragma unroll
            for (int bb = 0; bb < 2; bb++)
                #pragma unroll
                for (int w = 0; w < 3; w++) {
                    ulonglong2 a = *reinterpret_cast<const ulonglong2*>(HIX(b0 + bb, w) + 2 * k2);
                    ffma2(acc[bb][w][0], a.x, w0.x); ffma2(acc[bb][w][1], a.x, w0.y);
                    ffma2(acc[bb][w][0], a.y, w1.x); ffma2(acc[bb][w][1], a.y, w1.y);
                }
        }
        #pragma unroll
        for (int bb = 0; bb < 2; bb++)
            #pragma unroll
            for (int w = 0; w < 3; w++)
                *reinterpret_cast<float2*>(YI(b0 + bb, w) + c) =
                    make_float2(foldp(acc[bb][w][0]), foldp(acc[bb][w][1]));
    }
    __syncthreads();

    // ---- LN2 + head ----  (warp <-> batch)
    {
        const int b = warp;
        const int c4 = lane * 4;
        float4 fb  = *reinterpret_cast<const float4*>(&fc2_b[c4]);
        float4 gg  = *reinterpret_cast<const float4*>(&pf_g[c4]);
        float4 bb4 = *reinterpret_cast<const float4*>(&pf_b[c4]);
        float4 hw0 = *reinterpret_cast<const float4*>(&head_w[c4]);
        float4 hw1 = *reinterpret_cast<const float4*>(&head_w[D + c4]);
        const float hb0 = head_b[0], hb1 = head_b[1];
        #pragma unroll
        for (int w = 0; w < 3; w++) {
            float4 v = *reinterpret_cast<float4*>(YI(b, w) + c4);
            float4 xr = *reinterpret_cast<float4*>(XI(b, w) + c4);
            float val0 = v.x + fb.x + xr.x, val1 = v.y + fb.y + xr.y;
            float val2 = v.z + fb.z + xr.z, val3 = v.w + fb.w + xr.w;
            float s  = val0 + val1 + val2 + val3;
            float s2 = val0*val0 + val1*val1 + val2*val2 + val3*val3;
            #pragma unroll
            for (int o = 16; o; o >>= 1) {
                s  += __shfl_xor_sync(0xffffffffu, s,  o);
                s2 += __shfl_xor_sync(0xffffffffu, s2, o);
            }
            float m  = s * (1.0f / D);
            float vv = s2 * (1.0f / D) - m * m;
            float rs = rsqrtf(vv + 1e-5f);
            float x0 = (val0 - m) * rs * gg.x + bb4.x;
            float x1 = (val1 - m) * rs * gg.y + bb4.y;
            float x2 = (val2 - m) * rs * gg.z + bb4.z;
            float x3 = (val3 - m) * rs * gg.w + bb4.w;
            float d0 = x0 * hw0.x + x1 * hw0.y + x2 * hw0.z + x3 * hw0.w;
            float d1 = x0 * hw1.x + x1 * hw1.y + x2 * hw1.z + x3 * hw1.w;
            #pragma unroll
            for (int o = 16; o; o >>= 1) {
                d0 += __shfl_xor_sync(0xffffffffu, d0, o);
                d1 += __shfl_xor_sync(0xffffffffu, d1, o);
            }
            if (lane == 0) {
                out[(bg0 + b) * 6 + w * 2 + 0] = d0 + hb0;
                out[(bg0 + b) * 6 + w * 2 + 1] = d1 + hb1;
            }
        }
    }
}

// ---------------- launch ----------------
extern "C" void kernel_launch(void* const* d_in, const int* in_sizes, int n_in,
                              void* d_out, int out_size)
{
    const float* track_left   = (const float*)d_in[0];
    const float* track_right  = (const float*)d_in[1];
    const float* coord_w      = (const float*)d_in[2];
    const float* coord_b      = (const float*)d_in[3];
    const float* pos_emb      = (const float*)d_in[4];
    const float* side_emb     = (const float*)d_in[5];
    const float* query_emb    = (const float*)d_in[6];
    const float* tokens_ln_g  = (const float*)d_in[7];
    const float* tokens_ln_b  = (const float*)d_in[8];
    const float* queries_ln_g = (const float*)d_in[9];
    const float* queries_ln_b = (const float*)d_in[10];
    const float* in_proj_w    = (const float*)d_in[11];
    const float* in_proj_b    = (const float*)d_in[12];
    const float* out_proj_w   = (const float*)d_in[13];
    const float* out_proj_b   = (const float*)d_in[14];
    const float* fc1_w        = (const float*)d_in[15];
    const float* fc1_b        = (const float*)d_in[16];
    const float* fc2_w        = (const float*)d_in[17];
    const float* fc2_b        = (const float*)d_in[18];
    const float* pa_g         = (const float*)d_in[19];
    const float* pa_b         = (const float*)d_in[20];
    const float* pf_g         = (const float*)d_in[21];
    const float* pf_b         = (const float*)d_in[22];
    const float* head_w       = (const float*)d_in[23];
    const float* head_b       = (const float*)d_in[24];
    float* out = (float*)d_out;

    const int nb = in_sizes[0] / (T10 * 2);   // 32768

    prep_weights<<<96, 256>>>(in_proj_w, out_proj_w, fc1_w, fc2_w);
    precompute_kernel<<<1, 128>>>(query_emb, queries_ln_g, queries_ln_b, in_proj_w, in_proj_b);

    attn_kernel<<<nb / GPA, TPA>>>(track_left, track_right, coord_w, coord_b,
                                   pos_emb, side_emb, tokens_ln_g, tokens_ln_b);

    cudaFuncSetAttribute(ffn_kernel, cudaFuncAttributeMaxDynamicSharedMemorySize, SMEMB_BYTES);
    ffn_kernel<<<nb / NB, TPB, SMEMB_BYTES>>>(in_proj_b, out_proj_b, fc1_b, fc2_b,
                                              pa_g, pa_b, pf_g, pf_b, head_w, head_b, out);
}